// round 2
// baseline (speedup 1.0000x reference)
#include <cuda_runtime.h>
#include <stdint.h>
#include <math.h>

// Problem dims
#define CC      10        // celltypes
#define NN      1000      // cells per type
#define GG      18000     // genes
#define NG4     4500      // GG/4
#define NDRAW   500       // TOTAL_COUNT
#define CHUNKS  50
#define RPC     10        // rows per chunk  (CHUNKS*RPC == NDRAW)
#define NBLK    18        // ceil(4500/256)

// ---------------- device scratch (no allocations allowed) ----------------
__device__ int     g_counts[CC];
__device__ int     g_offsets[CC];
__device__ int     g_rows[NDRAW];
__device__ float4  g_partial[CHUNKS * NG4];   // 3.6 MB
__device__ float4  g_z[NG4];
__device__ float4  g_zn[NG4];
__device__ double  g_bS[NBLK], g_bS2[NBLK];
__device__ float   g_bMin[NBLK], g_bMax[NBLK];
__device__ float   g_stats[2];   // mean, rstd
__device__ float   g_mm[2];      // lo, hi

// ---------------- threefry2x32 core (exact JAX implementation) ----------------
__device__ __forceinline__ uint32_t rotl32(uint32_t v, int r) {
    return (v << r) | (v >> (32 - r));
}

__device__ __forceinline__ void tf2x32(uint32_t k0, uint32_t k1,
                                       uint32_t x0, uint32_t x1,
                                       uint32_t& o0, uint32_t& o1) {
    uint32_t k2 = k0 ^ k1 ^ 0x1BD11BDAu;
    x0 += k0; x1 += k1;
    // group 1 (rotations a = 13,15,26,6)
    x0 += x1; x1 = rotl32(x1, 13); x1 ^= x0;
    x0 += x1; x1 = rotl32(x1, 15); x1 ^= x0;
    x0 += x1; x1 = rotl32(x1, 26); x1 ^= x0;
    x0 += x1; x1 = rotl32(x1,  6); x1 ^= x0;
    x0 += k1; x1 += k2 + 1u;
    // group 2 (rotations b = 17,29,16,24)
    x0 += x1; x1 = rotl32(x1, 17); x1 ^= x0;
    x0 += x1; x1 = rotl32(x1, 29); x1 ^= x0;
    x0 += x1; x1 = rotl32(x1, 16); x1 ^= x0;
    x0 += x1; x1 = rotl32(x1, 24); x1 ^= x0;
    x0 += k2; x1 += k0 + 2u;
    // group 3 (a)
    x0 += x1; x1 = rotl32(x1, 13); x1 ^= x0;
    x0 += x1; x1 = rotl32(x1, 15); x1 ^= x0;
    x0 += x1; x1 = rotl32(x1, 26); x1 ^= x0;
    x0 += x1; x1 = rotl32(x1,  6); x1 ^= x0;
    x0 += k0; x1 += k1 + 3u;
    // group 4 (b)
    x0 += x1; x1 = rotl32(x1, 17); x1 ^= x0;
    x0 += x1; x1 = rotl32(x1, 29); x1 ^= x0;
    x0 += x1; x1 = rotl32(x1, 16); x1 ^= x0;
    x0 += x1; x1 = rotl32(x1, 24); x1 ^= x0;
    x0 += k1; x1 += k2 + 4u;
    // group 5 (a)
    x0 += x1; x1 = rotl32(x1, 13); x1 ^= x0;
    x0 += x1; x1 = rotl32(x1, 15); x1 ^= x0;
    x0 += x1; x1 = rotl32(x1, 26); x1 ^= x0;
    x0 += x1; x1 = rotl32(x1,  6); x1 ^= x0;
    x0 += k2; x1 += k0 + 5u;
    o0 = x0; o1 = x1;
}

struct Key { uint32_t a, b; };

// ======== PARTITIONABLE-MODE derivations (jax_threefry_partitionable=True) ========
// split(key, n)[i]   = both output words of threefry(key, hi=0, lo=i)  (foldlike)
// random_bits(...)[i] = o0 ^ o1 of threefry(key, hi=0, lo=i)           (xor-fold, 32-bit)

__device__ __forceinline__ Key keyfold(Key k, uint32_t i) {
    Key r; tf2x32(k.a, k.b, 0u, i, r.a, r.b); return r;
}

__device__ __forceinline__ uint32_t bits_at(Key k, uint32_t i) {
    uint32_t o0, o1; tf2x32(k.a, k.b, 0u, i, o0, o1); return o0 ^ o1;
}

__device__ __forceinline__ uint32_t bits_scalar(Key k) { return bits_at(k, 0u); }

__device__ __forceinline__ void split2(Key k, Key& k1, Key& k2) {
    k1 = keyfold(k, 0u); k2 = keyfold(k, 1u);
}

__device__ __forceinline__ void split3(Key k, Key& k1, Key& k2, Key& k3) {
    k1 = keyfold(k, 0u); k2 = keyfold(k, 1u); k3 = keyfold(k, 2u);
}

__device__ __forceinline__ float u01f(uint32_t bits) {
    return __uint_as_float((bits >> 9) | 0x3f800000u) - 1.0f;
}

// XLA ErfInv f32 (Giles polynomial) — matches lax.erf_inv lowering
__device__ __forceinline__ float xla_erfinv(float x) {
    float w = -log1pf(-x * x);
    float p;
    if (w < 5.0f) {
        w = w - 2.5f;
        p = 2.81022636e-08f;
        p = fmaf(p, w, 3.43273939e-07f);
        p = fmaf(p, w, -3.5233877e-06f);
        p = fmaf(p, w, -4.39150654e-06f);
        p = fmaf(p, w, 0.00021858087f);
        p = fmaf(p, w, -0.00125372503f);
        p = fmaf(p, w, -0.00417768164f);
        p = fmaf(p, w, 0.246640727f);
        p = fmaf(p, w, 1.50140941f);
    } else {
        w = sqrtf(w) - 3.0f;
        p = -0.000200214257f;
        p = fmaf(p, w, 0.000100950558f);
        p = fmaf(p, w, 0.00134934322f);
        p = fmaf(p, w, -0.00367342844f);
        p = fmaf(p, w, 0.00573950773f);
        p = fmaf(p, w, -0.0076224613f);
        p = fmaf(p, w, 0.00943887047f);
        p = fmaf(p, w, 1.00167406f);
        p = fmaf(p, w, 2.83297682f);
    }
    return p * x;
}

// jax.random.normal scalar: uniform in [nextafter(-1,0), 1), sqrt(2)*erfinv
__device__ __forceinline__ float normal_scalar(Key k) {
    float f = u01f(bits_scalar(k));
    float u = f * 2.0f + (-0.99999994f);   // (hi-lo) rounds to 2.0f in f32
    u = fmaxf(-0.99999994f, u);
    return 1.41421356f * xla_erfinv(u);
}

// jax _gamma_one (Marsaglia–Tsang with boost), log_space=False
__device__ float gamma_one(Key key, float alpha) {
    bool  bm      = (alpha >= 1.0f);
    float alpha_b = bm ? alpha : (alpha + 1.0f);
    float d = alpha_b - 0.33333334f;
    float c = 0.33333334f / sqrtf(d);

    Key sub;
    split2(key, key, sub);
    float u_boost = fmaxf(0.0f, u01f(bits_scalar(sub)));

    float X = 0.0f, V = 1.0f, U = 2.0f;
    for (int it = 0; it < 1000; ++it) {
        bool c1 = (U >= 1.0f - 0.0331f * (X * X));
        bool c2 = (logf(U) >= 0.5f * X + (d + (-(d * V) + d * logf(V))));
        if (!(c1 && c2)) break;   // accepted
        Key knew, xk, Uk;
        split3(key, knew, xk, Uk);
        key = knew;
        float x = 0.0f, v = -1.0f;
        for (int jt = 0; jt < 1000 && v <= 0.0f; ++jt) {
            Key xk2, sk;
            split2(xk, xk2, sk);
            xk = xk2;
            x = normal_scalar(sk);
            v = 1.0f + x * c;
        }
        X = x * x;
        V = (v * v) * v;
        U = fmaxf(0.0f, u01f(bits_scalar(Uk)));
    }
    float sample = d * V;
    float boost  = bm ? 1.0f : powf(u_boost, 1.0f / alpha);
    return sample * boost;
}

// gumbel with uniform(minval=f32 tiny, maxval=1)
__device__ __forceinline__ float gumbelf(uint32_t bits) {
    float f = u01f(bits);
    float u = fmaxf(1.17549435e-38f, f + 1.17549435e-38f);
    return -logf(-logf(u));
}

// ------------- K1a: alpha, gamma, logits, 500 categorical draws -> counts -------------
__global__ __launch_bounds__(256)
void k_setup_counts(const float* __restrict__ x, const float* __restrict__ W,
                    const float* __restrict__ b) {
    __shared__ float s_alpha[CC];
    __shared__ float s_g[CC];
    __shared__ float s_logits[CC];
    __shared__ Key   s_kg, s_kc;
    __shared__ int   s_cnt[CC];
    int t = threadIdx.x;
    if (t < CC) s_cnt[t] = 0;

    // alpha[0, j] = relu(x[0] @ W + b)[j] + 1e-6  (plain f32 sequential dot)
    if (t < CC) {
        float a = b[t];
        for (int k = 0; k < 64; k++) a = fmaf(x[k], W[k * CC + t], a);
        a = fmaxf(a, 0.0f) + 1e-6f;
        s_alpha[t] = a;
    }
    if (t == 0) {
        Key key42; key42.a = 0u; key42.b = 42u;           // jax.random.key(42)
        Key kdir, ksub, kg, kc;
        split2(key42, kdir, ksub);                        // k_dir, k_sub
        split2(kdir, kg, kc);                             // kg, kc
        s_kg = kg; s_kc = kc;
    }
    __syncthreads();

    // gamma samples: keys = split(kg, 40) foldlike, flat row 0 -> j = 0..9
    if (t < CC) {
        Key gk = keyfold(s_kg, (uint32_t)t);
        s_g[t] = gamma_one(gk, s_alpha[t]);
    }
    __syncthreads();

    if (t == 0) {
        float s = 0.0f;
        for (int j = 0; j < CC; j++) s += s_g[j];
        for (int j = 0; j < CC; j++) s_logits[j] = logf(s_g[j] / s);
    }
    __syncthreads();

    // categorical draws t and t+250: gumbel bits at flat idx (t*40 + b*10 + k), b=0
    if (t < 250) {
        Key kc = s_kc;
        int besta = 0, bestb = 0;
        float va = 0.f, vb = 0.f;
        for (int k = 0; k < CC; k++) {
            uint32_t ia = (uint32_t)(t * 40 + k);
            uint32_t ib = (uint32_t)((t + 250) * 40 + k);
            float ga = gumbelf(bits_at(kc, ia)) + s_logits[k];   // draw t
            float gb = gumbelf(bits_at(kc, ib)) + s_logits[k];   // draw t+250
            if (k == 0) { va = ga; vb = gb; }
            else {
                if (ga > va) { va = ga; besta = k; }
                if (gb > vb) { vb = gb; bestb = k; }
            }
        }
        atomicAdd(&s_cnt[besta], 1);
        atomicAdd(&s_cnt[bestb], 1);
    }
    __syncthreads();

    if (t == 0) {
        int off = 0;
        for (int c = 0; c < CC; c++) {
            g_counts[c]  = s_cnt[c];
            g_offsets[c] = off;
            off += s_cnt[c];
        }
    }
}

// ------------- K1b: one stable-sort permutation per celltype -> selected rows -------------
__global__ __launch_bounds__(1024)
void k_perm() {
    __shared__ uint32_t s_bits[NN];
    __shared__ Key s_sub;
    int c = blockIdx.x;
    int t = threadIdx.x;

    if (t == 0) {
        Key key42; key42.a = 0u; key42.b = 42u;
        Key kdir, ksub;
        split2(key42, kdir, ksub);                       // need k_sub
        Key keyc = keyfold(ksub, (uint32_t)c);           // split(k_sub, 10)[c]
        Key knew, sub;
        split2(keyc, knew, sub);                         // _shuffle: 1 round for n=1000
        s_sub = sub;
    }
    __syncthreads();

    if (t < NN) s_bits[t] = bits_at(s_sub, (uint32_t)t); // sort_keys (xor-fold)
    __syncthreads();

    if (t < NN) {
        uint32_t mykey = s_bits[t];
        int rank = 0;
        for (int m = 0; m < NN; m++) {
            uint32_t km = s_bits[m];
            rank += (km < mykey) || (km == mykey && m < t);   // stable sort rank
        }
        int kc = g_counts[c];
        if (rank < kc) g_rows[g_offsets[c] + rank] = c * NN + t;
    }
}

// ------------- K2: sparse gather-sum of 500 rows (36 MB instead of 720 MB) -------------
__global__ __launch_bounds__(256)
void k_gather(const float4* __restrict__ sc) {
    int g4 = blockIdx.x * 256 + threadIdx.x;
    int ch = blockIdx.y;
    if (g4 >= NG4) return;
    float4 acc = make_float4(0.f, 0.f, 0.f, 0.f);
#pragma unroll
    for (int r = 0; r < RPC; r++) {
        long row = (long)g_rows[ch * RPC + r];
        float4 v = __ldg(&sc[row * NG4 + g4]);
        acc.x += v.x; acc.y += v.y; acc.z += v.z; acc.w += v.w;
    }
    g_partial[ch * NG4 + g4] = acc;
}

// ------------- K3: total -> z = log1p(total); block partial sum/sumsq (double) -------------
__global__ __launch_bounds__(256)
void k_z_stats() {
    int g4 = blockIdx.x * 256 + threadIdx.x;
    int t = threadIdx.x;
    double ls = 0.0, ls2 = 0.0;
    if (g4 < NG4) {
        float4 acc = make_float4(0.f, 0.f, 0.f, 0.f);
        for (int ch = 0; ch < CHUNKS; ch++) {
            float4 v = g_partial[ch * NG4 + g4];
            acc.x += v.x; acc.y += v.y; acc.z += v.z; acc.w += v.w;
        }
        float4 z;
        z.x = log1pf(acc.x); z.y = log1pf(acc.y);
        z.z = log1pf(acc.z); z.w = log1pf(acc.w);
        g_z[g4] = z;
        ls  = (double)z.x + (double)z.y + (double)z.z + (double)z.w;
        ls2 = (double)z.x * z.x + (double)z.y * z.y + (double)z.z * z.z + (double)z.w * z.w;
    }
    __shared__ double sA[256], sB[256];
    sA[t] = ls; sB[t] = ls2;
    __syncthreads();
    for (int s = 128; s > 0; s >>= 1) {
        if (t < s) { sA[t] += sA[t + s]; sB[t] += sB[t + s]; }
        __syncthreads();
    }
    if (t == 0) { g_bS[blockIdx.x] = sA[0]; g_bS2[blockIdx.x] = sB[0]; }
}

// ------------- K4: reduce stats -> mean, rstd -------------
__global__ void k_stats_reduce() {
    if (threadIdx.x == 0) {
        double S = 0.0, S2 = 0.0;
        for (int i = 0; i < NBLK; i++) { S += g_bS[i]; S2 += g_bS2[i]; }
        double mean = S / (double)GG;
        double var  = S2 / (double)GG - mean * mean;
        g_stats[0] = (float)mean;
        g_stats[1] = (float)(1.0 / sqrt(var + (double)1e-3f));
    }
}

// ------------- K5: affine (gamma/beta) + block min/max -------------
__global__ __launch_bounds__(256)
void k_affine_minmax(const float* __restrict__ gam, const float* __restrict__ bet) {
    int g4 = blockIdx.x * 256 + threadIdx.x;
    int t = threadIdx.x;
    float mean = g_stats[0], rstd = g_stats[1];
    float mn = 3.4e38f, mx = -3.4e38f;
    if (g4 < NG4) {
        float4 z = g_z[g4];
        int g = g4 * 4;
        float4 zn;
        zn.x = (z.x - mean) * rstd * gam[g + 0] + bet[g + 0];
        zn.y = (z.y - mean) * rstd * gam[g + 1] + bet[g + 1];
        zn.z = (z.z - mean) * rstd * gam[g + 2] + bet[g + 2];
        zn.w = (z.w - mean) * rstd * gam[g + 3] + bet[g + 3];
        g_zn[g4] = zn;
        mn = fminf(fminf(zn.x, zn.y), fminf(zn.z, zn.w));
        mx = fmaxf(fmaxf(zn.x, zn.y), fmaxf(zn.z, zn.w));
    }
    __shared__ float sMn[256], sMx[256];
    sMn[t] = mn; sMx[t] = mx;
    __syncthreads();
    for (int s = 128; s > 0; s >>= 1) {
        if (t < s) {
            sMn[t] = fminf(sMn[t], sMn[t + s]);
            sMx[t] = fmaxf(sMx[t], sMx[t + s]);
        }
        __syncthreads();
    }
    if (t == 0) { g_bMin[blockIdx.x] = sMn[0]; g_bMax[blockIdx.x] = sMx[0]; }
}

// ------------- K6: reduce min/max -------------
__global__ void k_mm_reduce() {
    if (threadIdx.x == 0) {
        float lo = 3.4e38f, hi = -3.4e38f;
        for (int i = 0; i < NBLK; i++) {
            lo = fminf(lo, g_bMin[i]);
            hi = fmaxf(hi, g_bMax[i]);
        }
        g_mm[0] = lo; g_mm[1] = hi;
    }
}

// ------------- K7: final minmax normalize -------------
__global__ __launch_bounds__(256)
void k_final(float4* __restrict__ out) {
    int g4 = blockIdx.x * 256 + threadIdx.x;
    if (g4 >= NG4) return;
    float lo = g_mm[0], hi = g_mm[1];
    float den = hi - lo;
    float4 zn = g_zn[g4];
    float4 o;
    if (den == 0.0f) {
        o = make_float4(0.f, 0.f, 0.f, 0.f);
    } else {
        o.x = (zn.x - lo) / den;
        o.y = (zn.y - lo) / den;
        o.z = (zn.z - lo) / den;
        o.w = (zn.w - lo) / den;
    }
    out[g4] = o;
}

extern "C" void kernel_launch(void* const* d_in, const int* in_sizes, int n_in,
                              void* d_out, int out_size) {
    const float* x   = (const float*)d_in[0];   // (4,64)
    const float* W   = (const float*)d_in[1];   // (64,10)
    const float* b   = (const float*)d_in[2];   // (10,)
    const float* sc  = (const float*)d_in[3];   // (10,1000,18000)
    const float* gam = (const float*)d_in[4];   // (18000,)
    const float* bet = (const float*)d_in[5];   // (18000,)

    k_setup_counts<<<1, 256>>>(x, W, b);
    k_perm<<<CC, 1024>>>();
    k_gather<<<dim3(NBLK, CHUNKS), 256>>>((const float4*)sc);
    k_z_stats<<<NBLK, 256>>>();
    k_stats_reduce<<<1, 32>>>();
    k_affine_minmax<<<NBLK, 256>>>(gam, bet);
    k_mm_reduce<<<1, 32>>>();
    k_final<<<NBLK, 256>>>((float4*)d_out);
}

// round 6
// speedup vs baseline: 1.6621x; 1.6621x over previous
#include <cuda_runtime.h>
#include <stdint.h>
#include <math.h>

// Problem dims
#define CC      10        // celltypes
#define NN      1000      // cells per type
#define GG      18000     // genes
#define NG4     4500      // GG/4
#define NDRAW   500       // TOTAL_COUNT
#define GPT     32        // g4 tiles per K_B block
#define GRID_B  141       // ceil(4500/32)
#define GRID_A  (CC * 8)  // 8 blocks per celltype

// ---------------- device scratch (no allocations allowed) ----------------
__device__ int     g_rows[NDRAW];        // selected flat rows (c*NN + n)
__device__ double  g_bS[GRID_B], g_bS2[GRID_B];
__device__ float   g_bMin[GRID_B], g_bMax[GRID_B];
__device__ float   g_stats[2];           // mean, rstd
__device__ float   g_mm[2];              // lo, hi
__device__ int     g_c1, g_c2, g_flag1, g_flag2;

// ---------------- threefry2x32 core (exact JAX implementation) ----------------
__device__ __forceinline__ uint32_t rotl32(uint32_t v, int r) {
    return (v << r) | (v >> (32 - r));
}

__device__ __forceinline__ void tf2x32(uint32_t k0, uint32_t k1,
                                       uint32_t x0, uint32_t x1,
                                       uint32_t& o0, uint32_t& o1) {
    uint32_t k2 = k0 ^ k1 ^ 0x1BD11BDAu;
    x0 += k0; x1 += k1;
    x0 += x1; x1 = rotl32(x1, 13); x1 ^= x0;
    x0 += x1; x1 = rotl32(x1, 15); x1 ^= x0;
    x0 += x1; x1 = rotl32(x1, 26); x1 ^= x0;
    x0 += x1; x1 = rotl32(x1,  6); x1 ^= x0;
    x0 += k1; x1 += k2 + 1u;
    x0 += x1; x1 = rotl32(x1, 17); x1 ^= x0;
    x0 += x1; x1 = rotl32(x1, 29); x1 ^= x0;
    x0 += x1; x1 = rotl32(x1, 16); x1 ^= x0;
    x0 += x1; x1 = rotl32(x1, 24); x1 ^= x0;
    x0 += k2; x1 += k0 + 2u;
    x0 += x1; x1 = rotl32(x1, 13); x1 ^= x0;
    x0 += x1; x1 = rotl32(x1, 15); x1 ^= x0;
    x0 += x1; x1 = rotl32(x1, 26); x1 ^= x0;
    x0 += x1; x1 = rotl32(x1,  6); x1 ^= x0;
    x0 += k0; x1 += k1 + 3u;
    x0 += x1; x1 = rotl32(x1, 17); x1 ^= x0;
    x0 += x1; x1 = rotl32(x1, 29); x1 ^= x0;
    x0 += x1; x1 = rotl32(x1, 16); x1 ^= x0;
    x0 += x1; x1 = rotl32(x1, 24); x1 ^= x0;
    x0 += k1; x1 += k2 + 4u;
    x0 += x1; x1 = rotl32(x1, 13); x1 ^= x0;
    x0 += x1; x1 = rotl32(x1, 15); x1 ^= x0;
    x0 += x1; x1 = rotl32(x1, 26); x1 ^= x0;
    x0 += x1; x1 = rotl32(x1,  6); x1 ^= x0;
    x0 += k2; x1 += k0 + 5u;
    o0 = x0; o1 = x1;
}

struct Key { uint32_t a, b; };

// ======== PARTITIONABLE-MODE derivations (jax_threefry_partitionable=True) ========
__device__ __forceinline__ Key keyfold(Key k, uint32_t i) {
    Key r; tf2x32(k.a, k.b, 0u, i, r.a, r.b); return r;
}
__device__ __forceinline__ uint32_t bits_at(Key k, uint32_t i) {
    uint32_t o0, o1; tf2x32(k.a, k.b, 0u, i, o0, o1); return o0 ^ o1;
}
__device__ __forceinline__ uint32_t bits_scalar(Key k) { return bits_at(k, 0u); }
__device__ __forceinline__ void split2(Key k, Key& k1, Key& k2) {
    k1 = keyfold(k, 0u); k2 = keyfold(k, 1u);
}
__device__ __forceinline__ void split3(Key k, Key& k1, Key& k2, Key& k3) {
    k1 = keyfold(k, 0u); k2 = keyfold(k, 1u); k3 = keyfold(k, 2u);
}

__device__ __forceinline__ float u01f(uint32_t bits) {
    return __uint_as_float((bits >> 9) | 0x3f800000u) - 1.0f;
}

// XLA ErfInv f32 (Giles polynomial)
__device__ __forceinline__ float xla_erfinv(float x) {
    float w = -log1pf(-x * x);
    float p;
    if (w < 5.0f) {
        w = w - 2.5f;
        p = 2.81022636e-08f;
        p = fmaf(p, w, 3.43273939e-07f);
        p = fmaf(p, w, -3.5233877e-06f);
        p = fmaf(p, w, -4.39150654e-06f);
        p = fmaf(p, w, 0.00021858087f);
        p = fmaf(p, w, -0.00125372503f);
        p = fmaf(p, w, -0.00417768164f);
        p = fmaf(p, w, 0.246640727f);
        p = fmaf(p, w, 1.50140941f);
    } else {
        w = sqrtf(w) - 3.0f;
        p = -0.000200214257f;
        p = fmaf(p, w, 0.000100950558f);
        p = fmaf(p, w, 0.00134934322f);
        p = fmaf(p, w, -0.00367342844f);
        p = fmaf(p, w, 0.00573950773f);
        p = fmaf(p, w, -0.0076224613f);
        p = fmaf(p, w, 0.00943887047f);
        p = fmaf(p, w, 1.00167406f);
        p = fmaf(p, w, 2.83297682f);
    }
    return p * x;
}

__device__ __forceinline__ float normal_scalar(Key k) {
    float f = u01f(bits_scalar(k));
    float u = f * 2.0f + (-0.99999994f);
    u = fmaxf(-0.99999994f, u);
    return 1.41421356f * xla_erfinv(u);
}

// jax _gamma_one (Marsaglia–Tsang with boost), log_space=False
__device__ float gamma_one(Key key, float alpha) {
    bool  bm      = (alpha >= 1.0f);
    float alpha_b = bm ? alpha : (alpha + 1.0f);
    float d = alpha_b - 0.33333334f;
    float c = 0.33333334f / sqrtf(d);

    Key sub;
    split2(key, key, sub);
    float u_boost = fmaxf(0.0f, u01f(bits_scalar(sub)));

    float X = 0.0f, V = 1.0f, U = 2.0f;
    for (int it = 0; it < 1000; ++it) {
        bool c1 = (U >= 1.0f - 0.0331f * (X * X));
        bool c2 = (logf(U) >= 0.5f * X + (d + (-(d * V) + d * logf(V))));
        if (!(c1 && c2)) break;   // accepted
        Key knew, xk, Uk;
        split3(key, knew, xk, Uk);
        key = knew;
        float x = 0.0f, v = -1.0f;
        for (int jt = 0; jt < 1000 && v <= 0.0f; ++jt) {
            Key xk2, sk;
            split2(xk, xk2, sk);
            xk = xk2;
            x = normal_scalar(sk);
            v = 1.0f + x * c;
        }
        X = x * x;
        V = (v * v) * v;
        U = fmaxf(0.0f, u01f(bits_scalar(Uk)));
    }
    float sample = d * V;
    float boost  = bm ? 1.0f : powf(u_boost, 1.0f / alpha);
    return sample * boost;
}

__device__ __forceinline__ float gumbelf(uint32_t bits) {
    float f = u01f(bits);
    float u = fmaxf(1.17549435e-38f, f + 1.17549435e-38f);
    return -logf(-logf(u));
}

// ============ K_A: counts + permutation ranks, fused (grid = 80 x 1024) ============
// Block b: celltype c = b/8, octant oct = b%8 of the N^2 rank comparisons.
// PRNG chain recomputed redundantly per block (deterministic, identical).
__global__ __launch_bounds__(1024)
void k_prep(const float* __restrict__ x, const float* __restrict__ W,
            const float* __restrict__ b) {
    __shared__ float    s_alpha[CC], s_g[CC], s_logits[CC];
    __shared__ int      s_cnt[CC], s_off[CC];
    __shared__ Key      s_kg, s_kc, s_sub;
    __shared__ uint32_t s_bits[NN];
    int t   = threadIdx.x;
    int c   = blockIdx.x >> 3;
    int oct = blockIdx.x & 7;

    // reset K_B barrier state for this graph replay
    if (blockIdx.x == 0 && t == 0) { g_c1 = 0; g_c2 = 0; g_flag1 = 0; g_flag2 = 0; }

    if (t < CC) {
        s_cnt[t] = 0;
        // alpha[0, j] = relu(x[0] @ W + b)[j] + 1e-6
        float a = b[t];
        for (int k = 0; k < 64; k++) a = fmaf(x[k], W[k * CC + t], a);
        s_alpha[t] = fmaxf(a, 0.0f) + 1e-6f;
    }
    if (t == 0) {
        Key key42; key42.a = 0u; key42.b = 42u;        // jax.random.key(42)
        Key kdir, ksub, kg, kc;
        split2(key42, kdir, ksub);                     // k_dir, k_sub
        split2(kdir, kg, kc);                          // kg, kc
        s_kg = kg; s_kc = kc;
        Key keyc = keyfold(ksub, (uint32_t)c);         // split(k_sub, 10)[c]
        Key knew, sub;
        split2(keyc, knew, sub);                       // _shuffle: 1 round for n=1000
        s_sub = sub;
    }
    __syncthreads();

    if (t < CC) s_g[t] = gamma_one(keyfold(s_kg, (uint32_t)t), s_alpha[t]);
    __syncthreads();

    if (t == 0) {
        float s = 0.0f;
        for (int j = 0; j < CC; j++) s += s_g[j];
        for (int j = 0; j < CC; j++) s_logits[j] = logf(s_g[j] / s);
    }
    __syncthreads();

    // sort bits for this celltype
    if (t < NN) s_bits[t] = bits_at(s_sub, (uint32_t)t);

    // 500 categorical draws (batch row b=0): bits at flat idx draw*40 + k
    if (t < NDRAW) {
        int best = 0; float vbest = 0.f;
        for (int k = 0; k < CC; k++) {
            float gv = gumbelf(bits_at(s_kc, (uint32_t)(t * 40 + k))) + s_logits[k];
            if (k == 0) { vbest = gv; }
            else if (gv > vbest) { vbest = gv; best = k; }
        }
        atomicAdd(&s_cnt[best], 1);
    }
    __syncthreads();

    if (t == 0) {
        int off = 0;
        for (int j = 0; j < CC; j++) { s_off[j] = off; off += s_cnt[j]; }
    }
    __syncthreads();

    // stable-sort rank: element e = oct*125 + (t>>3); slice j = t&7 covers m in [j*125,(j+1)*125)
    int el = t >> 3, j = t & 7;
    if (el < 125) {
        int e = oct * 125 + el;
        uint32_t mykey = s_bits[e];
        int m0 = j * 125, m1 = m0 + 125;
        int rank = 0;
        #pragma unroll 5
        for (int m = m0; m < m1; m++) {
            uint32_t km = s_bits[m];
            rank += (km < mykey) || (km == mykey && m < e);
        }
        rank += __shfl_down_sync(0xffffffffu, rank, 4);
        rank += __shfl_down_sync(0xffffffffu, rank, 2);
        rank += __shfl_down_sync(0xffffffffu, rank, 1);
        if (j == 0 && rank < s_cnt[c]) g_rows[s_off[c] + rank] = c * NN + e;
    }
}

// ============ K_B: gather + log1p + LN stats + affine + minmax + normalize ============
// grid = 141 blocks x 256 threads (one block per SM -> all resident, spin barriers safe)
__global__ __launch_bounds__(256)
void k_fused(const float4* __restrict__ sc, const float4* __restrict__ gam4,
             const float4* __restrict__ bet4, float4* __restrict__ out4) {
    __shared__ int    s_rows[NDRAW];     // row * NG4
    __shared__ float4 s_acc[8][GPT];
    __shared__ int    s_last;

    int t   = threadIdx.x;
    int bid = blockIdx.x;
    int s   = t >> 5;        // row-split 0..7
    int gl  = t & 31;        // g4 within tile
    int g4  = bid * GPT + gl;
    bool valid = (g4 < NG4);

    for (int i = t; i < NDRAW; i += 256) s_rows[i] = g_rows[i] * NG4;
    __syncthreads();

    // ---- phase 1: gather-sum 500 selected rows (36 MB total read) ----
    float4 acc = make_float4(0.f, 0.f, 0.f, 0.f);
    if (valid) {
        #pragma unroll 8
        for (int r = s; r < NDRAW; r += 8) {
            float4 v = __ldg(&sc[(long)(s_rows[r] + g4)]);
            acc.x += v.x; acc.y += v.y; acc.z += v.z; acc.w += v.w;
        }
    }
    s_acc[s][gl] = acc;
    __syncthreads();

    // ---- phase 2: z = log1p(total), block partial sums (double) ----
    float4 z = make_float4(0.f, 0.f, 0.f, 0.f);
    if (t < 32) {
        float4 tot = make_float4(0.f, 0.f, 0.f, 0.f);
        #pragma unroll
        for (int q = 0; q < 8; q++) {
            float4 v = s_acc[q][t];
            tot.x += v.x; tot.y += v.y; tot.z += v.z; tot.w += v.w;
        }
        z.x = log1pf(tot.x); z.y = log1pf(tot.y);
        z.z = log1pf(tot.z); z.w = log1pf(tot.w);
        double ls = 0.0, ls2 = 0.0;
        if (valid) {
            ls  = (double)z.x + (double)z.y + (double)z.z + (double)z.w;
            ls2 = (double)z.x * z.x + (double)z.y * z.y
                + (double)z.z * z.z + (double)z.w * z.w;
        }
        ls  += __shfl_down_sync(0xffffffffu, ls, 16);
        ls2 += __shfl_down_sync(0xffffffffu, ls2, 16);
        ls  += __shfl_down_sync(0xffffffffu, ls, 8);
        ls2 += __shfl_down_sync(0xffffffffu, ls2, 8);
        ls  += __shfl_down_sync(0xffffffffu, ls, 4);
        ls2 += __shfl_down_sync(0xffffffffu, ls2, 4);
        ls  += __shfl_down_sync(0xffffffffu, ls, 2);
        ls2 += __shfl_down_sync(0xffffffffu, ls2, 2);
        ls  += __shfl_down_sync(0xffffffffu, ls, 1);
        ls2 += __shfl_down_sync(0xffffffffu, ls2, 1);
        if (t == 0) { g_bS[bid] = ls; g_bS2[bid] = ls2; }
    }
    __syncthreads();

    // ---- grid barrier 1: mean / rstd ----
    if (t == 0) {
        __threadfence();
        s_last = (atomicAdd(&g_c1, 1) == GRID_B - 1) ? 1 : 0;
    }
    __syncthreads();
    if (s_last) {
        if (t < 32) {
            double S = 0.0, S2 = 0.0;
            for (int i = t; i < GRID_B; i += 32) {
                S  += ((volatile double*)g_bS)[i];
                S2 += ((volatile double*)g_bS2)[i];
            }
            S  += __shfl_down_sync(0xffffffffu, S, 16);
            S2 += __shfl_down_sync(0xffffffffu, S2, 16);
            S  += __shfl_down_sync(0xffffffffu, S, 8);
            S2 += __shfl_down_sync(0xffffffffu, S2, 8);
            S  += __shfl_down_sync(0xffffffffu, S, 4);
            S2 += __shfl_down_sync(0xffffffffu, S2, 4);
            S  += __shfl_down_sync(0xffffffffu, S, 2);
            S2 += __shfl_down_sync(0xffffffffu, S2, 2);
            S  += __shfl_down_sync(0xffffffffu, S, 1);
            S2 += __shfl_down_sync(0xffffffffu, S2, 1);
            if (t == 0) {
                double mean = S / (double)GG;
                double var  = S2 / (double)GG - mean * mean;
                ((volatile float*)g_stats)[0] = (float)mean;
                ((volatile float*)g_stats)[1] = (float)(1.0 / sqrt(var + (double)1e-3f));
                __threadfence();
                atomicExch(&g_flag1, 1);
            }
        }
    } else if (t == 0) {
        while (atomicAdd(&g_flag1, 0) == 0) __nanosleep(40);
    }
    __syncthreads();
    float mean = ((volatile float*)g_stats)[0];
    float rstd = ((volatile float*)g_stats)[1];

    // ---- phase 3: affine + block min/max ----
    float4 zn = make_float4(0.f, 0.f, 0.f, 0.f);
    if (t < 32) {
        float mn = 3.4e38f, mx = -3.4e38f;
        if (valid) {
            float4 gm = __ldg(&gam4[g4]);
            float4 bt = __ldg(&bet4[g4]);
            zn.x = (z.x - mean) * rstd * gm.x + bt.x;
            zn.y = (z.y - mean) * rstd * gm.y + bt.y;
            zn.z = (z.z - mean) * rstd * gm.z + bt.z;
            zn.w = (z.w - mean) * rstd * gm.w + bt.w;
            mn = fminf(fminf(zn.x, zn.y), fminf(zn.z, zn.w));
            mx = fmaxf(fmaxf(zn.x, zn.y), fmaxf(zn.z, zn.w));
        }
        #pragma unroll
        for (int o = 16; o > 0; o >>= 1) {
            mn = fminf(mn, __shfl_down_sync(0xffffffffu, mn, o));
            mx = fmaxf(mx, __shfl_down_sync(0xffffffffu, mx, o));
        }
        if (t == 0) { g_bMin[bid] = mn; g_bMax[bid] = mx; }
    }
    __syncthreads();

    // ---- grid barrier 2: global min / max ----
    if (t == 0) {
        __threadfence();
        s_last = (atomicAdd(&g_c2, 1) == GRID_B - 1) ? 1 : 0;
    }
    __syncthreads();
    if (s_last) {
        if (t < 32) {
            float mn = 3.4e38f, mx = -3.4e38f;
            for (int i = t; i < GRID_B; i += 32) {
                mn = fminf(mn, ((volatile float*)g_bMin)[i]);
                mx = fmaxf(mx, ((volatile float*)g_bMax)[i]);
            }
            #pragma unroll
            for (int o = 16; o > 0; o >>= 1) {
                mn = fminf(mn, __shfl_down_sync(0xffffffffu, mn, o));
                mx = fmaxf(mx, __shfl_down_sync(0xffffffffu, mx, o));
            }
            if (t == 0) {
                ((volatile float*)g_mm)[0] = mn;
                ((volatile float*)g_mm)[1] = mx;
                __threadfence();
                atomicExch(&g_flag2, 1);
            }
        }
    } else if (t == 0) {
        while (atomicAdd(&g_flag2, 0) == 0) __nanosleep(40);
    }
    __syncthreads();

    // ---- phase 4: min-max normalize, write out ----
    if (t < 32 && valid) {
        float lo  = ((volatile float*)g_mm)[0];
        float hi  = ((volatile float*)g_mm)[1];
        float den = hi - lo;
        float4 o;
        if (den == 0.0f) {
            o = make_float4(0.f, 0.f, 0.f, 0.f);
        } else {
            o.x = (zn.x - lo) / den;
            o.y = (zn.y - lo) / den;
            o.z = (zn.z - lo) / den;
            o.w = (zn.w - lo) / den;
        }
        out4[g4] = o;
    }
}

extern "C" void kernel_launch(void* const* d_in, const int* in_sizes, int n_in,
                              void* d_out, int out_size) {
    const float* x   = (const float*)d_in[0];   // (4,64)
    const float* W   = (const float*)d_in[1];   // (64,10)
    const float* b   = (const float*)d_in[2];   // (10,)
    const float* sc  = (const float*)d_in[3];   // (10,1000,18000)
    const float* gam = (const float*)d_in[4];   // (18000,)
    const float* bet = (const float*)d_in[5];   // (18000,)

    k_prep<<<GRID_A, 1024>>>(x, W, b);
    k_fused<<<GRID_B, 256>>>((const float4*)sc, (const float4*)gam,
                             (const float4*)bet, (float4*)d_out);
}

// round 7
// speedup vs baseline: 1.6664x; 1.0026x over previous
#include <cuda_runtime.h>
#include <stdint.h>
#include <math.h>

// Problem dims
#define CC      10        // celltypes
#define NN      1000      // cells per type
#define GG      18000     // genes
#define NG4     4500      // GG/4
#define NDRAW   500       // TOTAL_COUNT
#define GPT     32        // g4 tiles per K_B block
#define GRID_B  141       // ceil(4500/32)
#define GRID_A  (CC * 8)  // 8 blocks per celltype
#define NWARP   32        // warps per K_B block

// ---------------- device scratch (no allocations allowed) ----------------
__device__ int     g_rows[NDRAW];        // selected flat rows (c*NN + n)
__device__ double  g_bS[GRID_B], g_bS2[GRID_B];
__device__ float   g_bMin[GRID_B], g_bMax[GRID_B];
__device__ float   g_stats[2];           // mean, rstd
__device__ float   g_mm[2];              // lo, hi
__device__ int     g_c1, g_c2, g_flag1, g_flag2;

// ---------------- threefry2x32 core (exact JAX implementation) ----------------
__device__ __forceinline__ uint32_t rotl32(uint32_t v, int r) {
    return (v << r) | (v >> (32 - r));
}

__device__ __forceinline__ void tf2x32(uint32_t k0, uint32_t k1,
                                       uint32_t x0, uint32_t x1,
                                       uint32_t& o0, uint32_t& o1) {
    uint32_t k2 = k0 ^ k1 ^ 0x1BD11BDAu;
    x0 += k0; x1 += k1;
    x0 += x1; x1 = rotl32(x1, 13); x1 ^= x0;
    x0 += x1; x1 = rotl32(x1, 15); x1 ^= x0;
    x0 += x1; x1 = rotl32(x1, 26); x1 ^= x0;
    x0 += x1; x1 = rotl32(x1,  6); x1 ^= x0;
    x0 += k1; x1 += k2 + 1u;
    x0 += x1; x1 = rotl32(x1, 17); x1 ^= x0;
    x0 += x1; x1 = rotl32(x1, 29); x1 ^= x0;
    x0 += x1; x1 = rotl32(x1, 16); x1 ^= x0;
    x0 += x1; x1 = rotl32(x1, 24); x1 ^= x0;
    x0 += k2; x1 += k0 + 2u;
    x0 += x1; x1 = rotl32(x1, 13); x1 ^= x0;
    x0 += x1; x1 = rotl32(x1, 15); x1 ^= x0;
    x0 += x1; x1 = rotl32(x1, 26); x1 ^= x0;
    x0 += x1; x1 = rotl32(x1,  6); x1 ^= x0;
    x0 += k0; x1 += k1 + 3u;
    x0 += x1; x1 = rotl32(x1, 17); x1 ^= x0;
    x0 += x1; x1 = rotl32(x1, 29); x1 ^= x0;
    x0 += x1; x1 = rotl32(x1, 16); x1 ^= x0;
    x0 += x1; x1 = rotl32(x1, 24); x1 ^= x0;
    x0 += k1; x1 += k2 + 4u;
    x0 += x1; x1 = rotl32(x1, 13); x1 ^= x0;
    x0 += x1; x1 = rotl32(x1, 15); x1 ^= x0;
    x0 += x1; x1 = rotl32(x1, 26); x1 ^= x0;
    x0 += x1; x1 = rotl32(x1,  6); x1 ^= x0;
    x0 += k2; x1 += k0 + 5u;
    o0 = x0; o1 = x1;
}

struct Key { uint32_t a, b; };

// ======== PARTITIONABLE-MODE derivations (jax_threefry_partitionable=True) ========
__device__ __forceinline__ Key keyfold(Key k, uint32_t i) {
    Key r; tf2x32(k.a, k.b, 0u, i, r.a, r.b); return r;
}
__device__ __forceinline__ uint32_t bits_at(Key k, uint32_t i) {
    uint32_t o0, o1; tf2x32(k.a, k.b, 0u, i, o0, o1); return o0 ^ o1;
}
__device__ __forceinline__ uint32_t bits_scalar(Key k) { return bits_at(k, 0u); }
__device__ __forceinline__ void split2(Key k, Key& k1, Key& k2) {
    k1 = keyfold(k, 0u); k2 = keyfold(k, 1u);
}
__device__ __forceinline__ void split3(Key k, Key& k1, Key& k2, Key& k3) {
    k1 = keyfold(k, 0u); k2 = keyfold(k, 1u); k3 = keyfold(k, 2u);
}

__device__ __forceinline__ float u01f(uint32_t bits) {
    return __uint_as_float((bits >> 9) | 0x3f800000u) - 1.0f;
}

// XLA ErfInv f32 (Giles polynomial)
__device__ __forceinline__ float xla_erfinv(float x) {
    float w = -log1pf(-x * x);
    float p;
    if (w < 5.0f) {
        w = w - 2.5f;
        p = 2.81022636e-08f;
        p = fmaf(p, w, 3.43273939e-07f);
        p = fmaf(p, w, -3.5233877e-06f);
        p = fmaf(p, w, -4.39150654e-06f);
        p = fmaf(p, w, 0.00021858087f);
        p = fmaf(p, w, -0.00125372503f);
        p = fmaf(p, w, -0.00417768164f);
        p = fmaf(p, w, 0.246640727f);
        p = fmaf(p, w, 1.50140941f);
    } else {
        w = sqrtf(w) - 3.0f;
        p = -0.000200214257f;
        p = fmaf(p, w, 0.000100950558f);
        p = fmaf(p, w, 0.00134934322f);
        p = fmaf(p, w, -0.00367342844f);
        p = fmaf(p, w, 0.00573950773f);
        p = fmaf(p, w, -0.0076224613f);
        p = fmaf(p, w, 0.00943887047f);
        p = fmaf(p, w, 1.00167406f);
        p = fmaf(p, w, 2.83297682f);
    }
    return p * x;
}

__device__ __forceinline__ float normal_scalar(Key k) {
    float f = u01f(bits_scalar(k));
    float u = f * 2.0f + (-0.99999994f);
    u = fmaxf(-0.99999994f, u);
    return 1.41421356f * xla_erfinv(u);
}

// jax _gamma_one (Marsaglia–Tsang with boost), log_space=False
__device__ float gamma_one(Key key, float alpha) {
    bool  bm      = (alpha >= 1.0f);
    float alpha_b = bm ? alpha : (alpha + 1.0f);
    float d = alpha_b - 0.33333334f;
    float c = 0.33333334f / sqrtf(d);

    Key sub;
    split2(key, key, sub);
    float u_boost = fmaxf(0.0f, u01f(bits_scalar(sub)));

    float X = 0.0f, V = 1.0f, U = 2.0f;
    for (int it = 0; it < 1000; ++it) {
        bool c1 = (U >= 1.0f - 0.0331f * (X * X));
        bool c2 = (logf(U) >= 0.5f * X + (d + (-(d * V) + d * logf(V))));
        if (!(c1 && c2)) break;   // accepted
        Key knew, xk, Uk;
        split3(key, knew, xk, Uk);
        key = knew;
        float x = 0.0f, v = -1.0f;
        for (int jt = 0; jt < 1000 && v <= 0.0f; ++jt) {
            Key xk2, sk;
            split2(xk, xk2, sk);
            xk = xk2;
            x = normal_scalar(sk);
            v = 1.0f + x * c;
        }
        X = x * x;
        V = (v * v) * v;
        U = fmaxf(0.0f, u01f(bits_scalar(Uk)));
    }
    float sample = d * V;
    float boost  = bm ? 1.0f : powf(u_boost, 1.0f / alpha);
    return sample * boost;
}

__device__ __forceinline__ float gumbelf(uint32_t bits) {
    float f = u01f(bits);
    float u = fmaxf(1.17549435e-38f, f + 1.17549435e-38f);
    return -logf(-logf(u));
}

// ============ K_A: counts + permutation ranks, fused (grid = 80 x 1024) ============
__global__ __launch_bounds__(1024)
void k_prep(const float* __restrict__ x, const float* __restrict__ W,
            const float* __restrict__ b) {
    __shared__ float    s_alpha[CC], s_g[CC], s_logits[CC];
    __shared__ int      s_cnt[CC], s_off[CC];
    __shared__ Key      s_kg, s_kc, s_sub;
    __shared__ uint32_t s_bits[NN];
    int t   = threadIdx.x;
    int c   = blockIdx.x >> 3;
    int oct = blockIdx.x & 7;

    // reset K_B barrier state for this graph replay
    if (blockIdx.x == 0 && t == 0) { g_c1 = 0; g_c2 = 0; g_flag1 = 0; g_flag2 = 0; }

    if (t < CC) {
        s_cnt[t] = 0;
        // alpha[0, j] = relu(x[0] @ W + b)[j] + 1e-6
        float a = b[t];
        for (int k = 0; k < 64; k++) a = fmaf(x[k], W[k * CC + t], a);
        s_alpha[t] = fmaxf(a, 0.0f) + 1e-6f;
    }
    if (t == 0) {
        Key key42; key42.a = 0u; key42.b = 42u;        // jax.random.key(42)
        Key kdir, ksub, kg, kc;
        split2(key42, kdir, ksub);                     // k_dir, k_sub
        split2(kdir, kg, kc);                          // kg, kc
        s_kg = kg; s_kc = kc;
        Key keyc = keyfold(ksub, (uint32_t)c);         // split(k_sub, 10)[c]
        Key knew, sub;
        split2(keyc, knew, sub);                       // _shuffle: 1 round for n=1000
        s_sub = sub;
    }
    __syncthreads();

    if (t < CC) s_g[t] = gamma_one(keyfold(s_kg, (uint32_t)t), s_alpha[t]);
    __syncthreads();

    if (t == 0) {
        float s = 0.0f;
        for (int j = 0; j < CC; j++) s += s_g[j];
        for (int j = 0; j < CC; j++) s_logits[j] = logf(s_g[j] / s);
    }
    __syncthreads();

    // sort bits for this celltype
    if (t < NN) s_bits[t] = bits_at(s_sub, (uint32_t)t);

    // 500 categorical draws (batch row b=0): bits at flat idx draw*40 + k
    if (t < NDRAW) {
        int best = 0; float vbest = 0.f;
        for (int k = 0; k < CC; k++) {
            float gv = gumbelf(bits_at(s_kc, (uint32_t)(t * 40 + k))) + s_logits[k];
            if (k == 0) { vbest = gv; }
            else if (gv > vbest) { vbest = gv; best = k; }
        }
        atomicAdd(&s_cnt[best], 1);
    }
    __syncthreads();

    if (t == 0) {
        int off = 0;
        for (int j = 0; j < CC; j++) { s_off[j] = off; off += s_cnt[j]; }
    }
    __syncthreads();

    // stable-sort rank: element e = oct*125 + (t>>3); slice j = t&7 covers m in [j*125,(j+1)*125)
    int el = t >> 3, j = t & 7;
    if (el < 125) {
        int e = oct * 125 + el;
        uint32_t mykey = s_bits[e];
        int m0 = j * 125, m1 = m0 + 125;
        int rank = 0;
        #pragma unroll 5
        for (int m = m0; m < m1; m++) {
            uint32_t km = s_bits[m];
            rank += (km < mykey) || (km == mykey && m < e);
        }
        rank += __shfl_down_sync(0xffffffffu, rank, 4);
        rank += __shfl_down_sync(0xffffffffu, rank, 2);
        rank += __shfl_down_sync(0xffffffffu, rank, 1);
        if (j == 0 && rank < s_cnt[c]) g_rows[s_off[c] + rank] = c * NN + e;
    }
}

// ============ K_B: gather + log1p + LN stats + affine + minmax + normalize ============
// grid = 141 blocks x 1024 threads (one block per SM -> all resident, spin barriers safe)
// 32 warps: warp w gathers rows r ≡ w (mod 32) for the block's 32 g4 lanes.
__global__ __launch_bounds__(1024)
void k_fused(const float4* __restrict__ sc, const float4* __restrict__ gam4,
             const float4* __restrict__ bet4, float4* __restrict__ out4) {
    __shared__ int    s_rows[NDRAW];            // row * NG4
    __shared__ float4 s_acc[NWARP][GPT];        // 16 KB partials
    __shared__ int    s_last;

    int t    = threadIdx.x;
    int bid  = blockIdx.x;
    int w    = t >> 5;       // warp 0..31 (row-split)
    int lane = t & 31;       // g4 within tile
    int g4   = bid * GPT + lane;
    bool valid = (g4 < NG4);

    for (int i = t; i < NDRAW; i += 1024) s_rows[i] = g_rows[i] * NG4;
    __syncthreads();

    // ---- phase 1: gather-sum 500 selected rows (36 MB total read) ----
    float4 acc = make_float4(0.f, 0.f, 0.f, 0.f);
    if (valid) {
        #pragma unroll 4
        for (int r = w; r < NDRAW; r += NWARP) {
            float4 v = __ldg(&sc[(long)(s_rows[r] + g4)]);
            acc.x += v.x; acc.y += v.y; acc.z += v.z; acc.w += v.w;
        }
    }
    s_acc[w][lane] = acc;
    __syncthreads();

    // ---- phase 2: z = log1p(total), block partial sums (double) ----
    float4 z = make_float4(0.f, 0.f, 0.f, 0.f);
    if (t < 32) {
        float4 tot = make_float4(0.f, 0.f, 0.f, 0.f);
        #pragma unroll
        for (int q = 0; q < NWARP; q++) {
            float4 v = s_acc[q][t];
            tot.x += v.x; tot.y += v.y; tot.z += v.z; tot.w += v.w;
        }
        z.x = log1pf(tot.x); z.y = log1pf(tot.y);
        z.z = log1pf(tot.z); z.w = log1pf(tot.w);
        double ls = 0.0, ls2 = 0.0;
        if (valid) {
            ls  = (double)z.x + (double)z.y + (double)z.z + (double)z.w;
            ls2 = (double)z.x * z.x + (double)z.y * z.y
                + (double)z.z * z.z + (double)z.w * z.w;
        }
        #pragma unroll
        for (int o = 16; o > 0; o >>= 1) {
            ls  += __shfl_down_sync(0xffffffffu, ls, o);
            ls2 += __shfl_down_sync(0xffffffffu, ls2, o);
        }
        if (t == 0) { g_bS[bid] = ls; g_bS2[bid] = ls2; }
    }
    __syncthreads();

    // ---- grid barrier 1: mean / rstd ----
    if (t == 0) {
        __threadfence();
        s_last = (atomicAdd(&g_c1, 1) == GRID_B - 1) ? 1 : 0;
    }
    __syncthreads();
    if (s_last) {
        if (t < 32) {
            double S = 0.0, S2 = 0.0;
            for (int i = t; i < GRID_B; i += 32) {
                S  += ((volatile double*)g_bS)[i];
                S2 += ((volatile double*)g_bS2)[i];
            }
            #pragma unroll
            for (int o = 16; o > 0; o >>= 1) {
                S  += __shfl_down_sync(0xffffffffu, S, o);
                S2 += __shfl_down_sync(0xffffffffu, S2, o);
            }
            if (t == 0) {
                double mean = S / (double)GG;
                double var  = S2 / (double)GG - mean * mean;
                ((volatile float*)g_stats)[0] = (float)mean;
                ((volatile float*)g_stats)[1] = (float)(1.0 / sqrt(var + (double)1e-3f));
                __threadfence();
                atomicExch(&g_flag1, 1);
            }
        }
    } else if (t == 0) {
        while (atomicAdd(&g_flag1, 0) == 0) __nanosleep(40);
    }
    __syncthreads();
    float mean = ((volatile float*)g_stats)[0];
    float rstd = ((volatile float*)g_stats)[1];

    // ---- phase 3: affine + block min/max ----
    float4 zn = make_float4(0.f, 0.f, 0.f, 0.f);
    if (t < 32) {
        float mn = 3.4e38f, mx = -3.4e38f;
        if (valid) {
            float4 gm = __ldg(&gam4[g4]);
            float4 bt = __ldg(&bet4[g4]);
            zn.x = (z.x - mean) * rstd * gm.x + bt.x;
            zn.y = (z.y - mean) * rstd * gm.y + bt.y;
            zn.z = (z.z - mean) * rstd * gm.z + bt.z;
            zn.w = (z.w - mean) * rstd * gm.w + bt.w;
            mn = fminf(fminf(zn.x, zn.y), fminf(zn.z, zn.w));
            mx = fmaxf(fmaxf(zn.x, zn.y), fmaxf(zn.z, zn.w));
        }
        #pragma unroll
        for (int o = 16; o > 0; o >>= 1) {
            mn = fminf(mn, __shfl_down_sync(0xffffffffu, mn, o));
            mx = fmaxf(mx, __shfl_down_sync(0xffffffffu, mx, o));
        }
        if (t == 0) { g_bMin[bid] = mn; g_bMax[bid] = mx; }
    }
    __syncthreads();

    // ---- grid barrier 2: global min / max ----
    if (t == 0) {
        __threadfence();
        s_last = (atomicAdd(&g_c2, 1) == GRID_B - 1) ? 1 : 0;
    }
    __syncthreads();
    if (s_last) {
        if (t < 32) {
            float mn = 3.4e38f, mx = -3.4e38f;
            for (int i = t; i < GRID_B; i += 32) {
                mn = fminf(mn, ((volatile float*)g_bMin)[i]);
                mx = fmaxf(mx, ((volatile float*)g_bMax)[i]);
            }
            #pragma unroll
            for (int o = 16; o > 0; o >>= 1) {
                mn = fminf(mn, __shfl_down_sync(0xffffffffu, mn, o));
                mx = fmaxf(mx, __shfl_down_sync(0xffffffffu, mx, o));
            }
            if (t == 0) {
                ((volatile float*)g_mm)[0] = mn;
                ((volatile float*)g_mm)[1] = mx;
                __threadfence();
                atomicExch(&g_flag2, 1);
            }
        }
    } else if (t == 0) {
        while (atomicAdd(&g_flag2, 0) == 0) __nanosleep(40);
    }
    __syncthreads();

    // ---- phase 4: min-max normalize, write out ----
    if (t < 32 && valid) {
        float lo  = ((volatile float*)g_mm)[0];
        float hi  = ((volatile float*)g_mm)[1];
        float den = hi - lo;
        float4 o;
        if (den == 0.0f) {
            o = make_float4(0.f, 0.f, 0.f, 0.f);
        } else {
            o.x = (zn.x - lo) / den;
            o.y = (zn.y - lo) / den;
            o.z = (zn.z - lo) / den;
            o.w = (zn.w - lo) / den;
        }
        out4[g4] = o;
    }
}

extern "C" void kernel_launch(void* const* d_in, const int* in_sizes, int n_in,
                              void* d_out, int out_size) {
    const float* x   = (const float*)d_in[0];   // (4,64)
    const float* W   = (const float*)d_in[1];   // (64,10)
    const float* b   = (const float*)d_in[2];   // (10,)
    const float* sc  = (const float*)d_in[3];   // (10,1000,18000)
    const float* gam = (const float*)d_in[4];   // (18000,)
    const float* bet = (const float*)d_in[5];   // (18000,)

    k_prep<<<GRID_A, 1024>>>(x, W, b);
    k_fused<<<GRID_B, 1024>>>((const float4*)sc, (const float4*)gam,
                              (const float4*)bet, (float4*)d_out);
}

// round 17
// speedup vs baseline: 1.7473x; 1.0486x over previous
#include <cuda_runtime.h>
#include <stdint.h>
#include <math.h>

// Problem dims
#define CC      10        // celltypes
#define NN      1000      // cells per type
#define GG      18000     // genes
#define NG4     4500      // GG/4
#define NDRAW   500       // TOTAL_COUNT
#define GPT     32        // g4 tiles per K_B block
#define GRID_B  141       // ceil(4500/32)
#define GRID_A  (CC * 8)  // 8 blocks per celltype
#define NWARP   16        // warps per K_B block (512 threads)
#define RPW     32        // rows per warp (NWARP*RPW = 512 >= 500, tail weighted 0)

// ---------------- device scratch (no allocations allowed) ----------------
__device__ int     g_rows[NDRAW];        // selected flat rows (c*NN + n)
__device__ double  g_bS[GRID_B], g_bS2[GRID_B];
__device__ float   g_bMin[GRID_B], g_bMax[GRID_B];
__device__ float   g_stats[2];           // mean, rstd
__device__ float   g_mm[2];              // lo, hi
__device__ int     g_c1, g_c2, g_flag1, g_flag2;

// ---------------- threefry2x32 core (exact JAX implementation) ----------------
__device__ __forceinline__ uint32_t rotl32(uint32_t v, int r) {
    return (v << r) | (v >> (32 - r));
}

__device__ __forceinline__ void tf2x32(uint32_t k0, uint32_t k1,
                                       uint32_t x0, uint32_t x1,
                                       uint32_t& o0, uint32_t& o1) {
    uint32_t k2 = k0 ^ k1 ^ 0x1BD11BDAu;
    x0 += k0; x1 += k1;
    x0 += x1; x1 = rotl32(x1, 13); x1 ^= x0;
    x0 += x1; x1 = rotl32(x1, 15); x1 ^= x0;
    x0 += x1; x1 = rotl32(x1, 26); x1 ^= x0;
    x0 += x1; x1 = rotl32(x1,  6); x1 ^= x0;
    x0 += k1; x1 += k2 + 1u;
    x0 += x1; x1 = rotl32(x1, 17); x1 ^= x0;
    x0 += x1; x1 = rotl32(x1, 29); x1 ^= x0;
    x0 += x1; x1 = rotl32(x1, 16); x1 ^= x0;
    x0 += x1; x1 = rotl32(x1, 24); x1 ^= x0;
    x0 += k2; x1 += k0 + 2u;
    x0 += x1; x1 = rotl32(x1, 13); x1 ^= x0;
    x0 += x1; x1 = rotl32(x1, 15); x1 ^= x0;
    x0 += x1; x1 = rotl32(x1, 26); x1 ^= x0;
    x0 += x1; x1 = rotl32(x1,  6); x1 ^= x0;
    x0 += k0; x1 += k1 + 3u;
    x0 += x1; x1 = rotl32(x1, 17); x1 ^= x0;
    x0 += x1; x1 = rotl32(x1, 29); x1 ^= x0;
    x0 += x1; x1 = rotl32(x1, 16); x1 ^= x0;
    x0 += x1; x1 = rotl32(x1, 24); x1 ^= x0;
    x0 += k1; x1 += k2 + 4u;
    x0 += x1; x1 = rotl32(x1, 13); x1 ^= x0;
    x0 += x1; x1 = rotl32(x1, 15); x1 ^= x0;
    x0 += x1; x1 = rotl32(x1, 26); x1 ^= x0;
    x0 += x1; x1 = rotl32(x1,  6); x1 ^= x0;
    x0 += k2; x1 += k0 + 5u;
    o0 = x0; o1 = x1;
}

struct Key { uint32_t a, b; };

// ======== PARTITIONABLE-MODE derivations (jax_threefry_partitionable=True) ========
__device__ __forceinline__ Key keyfold(Key k, uint32_t i) {
    Key r; tf2x32(k.a, k.b, 0u, i, r.a, r.b); return r;
}
__device__ __forceinline__ uint32_t bits_at(Key k, uint32_t i) {
    uint32_t o0, o1; tf2x32(k.a, k.b, 0u, i, o0, o1); return o0 ^ o1;
}
__device__ __forceinline__ uint32_t bits_scalar(Key k) { return bits_at(k, 0u); }
__device__ __forceinline__ void split2(Key k, Key& k1, Key& k2) {
    k1 = keyfold(k, 0u); k2 = keyfold(k, 1u);
}
__device__ __forceinline__ void split3(Key k, Key& k1, Key& k2, Key& k3) {
    k1 = keyfold(k, 0u); k2 = keyfold(k, 1u); k3 = keyfold(k, 2u);
}

__device__ __forceinline__ float u01f(uint32_t bits) {
    return __uint_as_float((bits >> 9) | 0x3f800000u) - 1.0f;
}

// XLA ErfInv f32 (Giles polynomial)
__device__ __forceinline__ float xla_erfinv(float x) {
    float w = -log1pf(-x * x);
    float p;
    if (w < 5.0f) {
        w = w - 2.5f;
        p = 2.81022636e-08f;
        p = fmaf(p, w, 3.43273939e-07f);
        p = fmaf(p, w, -3.5233877e-06f);
        p = fmaf(p, w, -4.39150654e-06f);
        p = fmaf(p, w, 0.00021858087f);
        p = fmaf(p, w, -0.00125372503f);
        p = fmaf(p, w, -0.00417768164f);
        p = fmaf(p, w, 0.246640727f);
        p = fmaf(p, w, 1.50140941f);
    } else {
        w = sqrtf(w) - 3.0f;
        p = -0.000200214257f;
        p = fmaf(p, w, 0.000100950558f);
        p = fmaf(p, w, 0.00134934322f);
        p = fmaf(p, w, -0.00367342844f);
        p = fmaf(p, w, 0.00573950773f);
        p = fmaf(p, w, -0.0076224613f);
        p = fmaf(p, w, 0.00943887047f);
        p = fmaf(p, w, 1.00167406f);
        p = fmaf(p, w, 2.83297682f);
    }
    return p * x;
}

__device__ __forceinline__ float normal_scalar(Key k) {
    float f = u01f(bits_scalar(k));
    float u = f * 2.0f + (-0.99999994f);
    u = fmaxf(-0.99999994f, u);
    return 1.41421356f * xla_erfinv(u);
}

// jax _gamma_one (Marsaglia–Tsang with boost), log_space=False
__device__ float gamma_one(Key key, float alpha) {
    bool  bm      = (alpha >= 1.0f);
    float alpha_b = bm ? alpha : (alpha + 1.0f);
    float d = alpha_b - 0.33333334f;
    float c = 0.33333334f / sqrtf(d);

    Key sub;
    split2(key, key, sub);
    float u_boost = fmaxf(0.0f, u01f(bits_scalar(sub)));

    float X = 0.0f, V = 1.0f, U = 2.0f;
    for (int it = 0; it < 1000; ++it) {
        bool c1 = (U >= 1.0f - 0.0331f * (X * X));
        bool c2 = (logf(U) >= 0.5f * X + (d + (-(d * V) + d * logf(V))));
        if (!(c1 && c2)) break;   // accepted
        Key knew, xk, Uk;
        split3(key, knew, xk, Uk);
        key = knew;
        float x = 0.0f, v = -1.0f;
        for (int jt = 0; jt < 1000 && v <= 0.0f; ++jt) {
            Key xk2, sk;
            split2(xk, xk2, sk);
            xk = xk2;
            x = normal_scalar(sk);
            v = 1.0f + x * c;
        }
        X = x * x;
        V = (v * v) * v;
        U = fmaxf(0.0f, u01f(bits_scalar(Uk)));
    }
    float sample = d * V;
    float boost  = bm ? 1.0f : powf(u_boost, 1.0f / alpha);
    return sample * boost;
}

__device__ __forceinline__ float gumbelf(uint32_t bits) {
    float f = u01f(bits);
    float u = fmaxf(1.17549435e-38f, f + 1.17549435e-38f);
    return -logf(-logf(u));
}

// ============ K_A: counts + permutation ranks, fused (grid = 80 x 1024) ============
__global__ __launch_bounds__(1024)
void k_prep(const float* __restrict__ x, const float* __restrict__ W,
            const float* __restrict__ b) {
    __shared__ float    s_alpha[CC], s_g[CC], s_logits[CC];
    __shared__ int      s_cnt[CC], s_off[CC];
    __shared__ Key      s_kg, s_kc, s_sub;
    __shared__ uint32_t s_bits[NN];
    int t   = threadIdx.x;
    int c   = blockIdx.x >> 3;
    int oct = blockIdx.x & 7;

    // reset K_B barrier state for this graph replay
    if (blockIdx.x == 0 && t == 0) { g_c1 = 0; g_c2 = 0; g_flag1 = 0; g_flag2 = 0; }

    if (t < CC) {
        s_cnt[t] = 0;
        // alpha[0, j] = relu(x[0] @ W + b)[j] + 1e-6
        float a = b[t];
        for (int k = 0; k < 64; k++) a = fmaf(x[k], W[k * CC + t], a);
        s_alpha[t] = fmaxf(a, 0.0f) + 1e-6f;
    }
    if (t == 0) {
        Key key42; key42.a = 0u; key42.b = 42u;        // jax.random.key(42)
        Key kdir, ksub, kg, kc;
        split2(key42, kdir, ksub);                     // k_dir, k_sub
        split2(kdir, kg, kc);                          // kg, kc
        s_kg = kg; s_kc = kc;
        Key keyc = keyfold(ksub, (uint32_t)c);         // split(k_sub, 10)[c]
        Key knew, sub;
        split2(keyc, knew, sub);                       // _shuffle: 1 round for n=1000
        s_sub = sub;
    }
    __syncthreads();

    if (t < CC) s_g[t] = gamma_one(keyfold(s_kg, (uint32_t)t), s_alpha[t]);
    __syncthreads();

    if (t == 0) {
        float s = 0.0f;
        for (int j = 0; j < CC; j++) s += s_g[j];
        for (int j = 0; j < CC; j++) s_logits[j] = logf(s_g[j] / s);
    }
    __syncthreads();

    // sort bits for this celltype
    if (t < NN) s_bits[t] = bits_at(s_sub, (uint32_t)t);

    // 500 categorical draws (batch row b=0): bits at flat idx draw*40 + k
    if (t < NDRAW) {
        int best = 0; float vbest = 0.f;
        for (int k = 0; k < CC; k++) {
            float gv = gumbelf(bits_at(s_kc, (uint32_t)(t * 40 + k))) + s_logits[k];
            if (k == 0) { vbest = gv; }
            else if (gv > vbest) { vbest = gv; best = k; }
        }
        atomicAdd(&s_cnt[best], 1);
    }
    __syncthreads();

    if (t == 0) {
        int off = 0;
        for (int j = 0; j < CC; j++) { s_off[j] = off; off += s_cnt[j]; }
    }
    __syncthreads();

    // stable-sort rank: element e = oct*125 + (t>>3); slice j = t&7 covers m in [j*125,(j+1)*125)
    int el = t >> 3, j = t & 7;
    if (el < 125) {
        int e = oct * 125 + el;
        uint32_t mykey = s_bits[e];
        int m0 = j * 125, m1 = m0 + 125;
        int rank = 0;
        #pragma unroll 5
        for (int m = m0; m < m1; m++) {
            uint32_t km = s_bits[m];
            rank += (km < mykey) || (km == mykey && m < e);
        }
        rank += __shfl_down_sync(0xffffffffu, rank, 4);
        rank += __shfl_down_sync(0xffffffffu, rank, 2);
        rank += __shfl_down_sync(0xffffffffu, rank, 1);
        if (j == 0 && rank < s_cnt[c]) g_rows[s_off[c] + rank] = c * NN + e;
    }
}

// ============ K_B: gather + log1p + LN stats + affine + minmax + normalize ============
// grid = 141 blocks x 512 threads (one block per SM -> all resident, spin barriers safe)
// 16 warps: warp w owns rows [32w, 32w+32); 4 chunks of 8 loads buffered in registers
// (explicit MLP=8) before accumulating. Tail rows >= 500 clamp to row 499, weight 0.
__global__ __launch_bounds__(512)
void k_fused(const float4* __restrict__ sc, const float4* __restrict__ gam4,
             const float4* __restrict__ bet4, float4* __restrict__ out4) {
    __shared__ int    s_rows[NDRAW];            // row * NG4
    __shared__ float4 s_acc[NWARP][GPT];        // 8 KB partials
    __shared__ int    s_last;

    int t    = threadIdx.x;
    int bid  = blockIdx.x;
    int w    = t >> 5;       // warp 0..15 (row-split)
    int lane = t & 31;       // g4 within tile
    int g4   = bid * GPT + lane;
    bool valid = (g4 < NG4);

    for (int i = t; i < NDRAW; i += 512) s_rows[i] = g_rows[i] * NG4;
    __syncthreads();

    // ---- phase 1: gather-sum 500 selected rows (36 MB total read), MLP=8 ----
    float4 acc = make_float4(0.f, 0.f, 0.f, 0.f);
    if (valid) {
        int rbase = w * RPW;
        #pragma unroll
        for (int ch = 0; ch < RPW / 8; ch++) {
            int r0 = rbase + ch * 8;
            float4 v[8];
            #pragma unroll
            for (int j = 0; j < 8; j++) {
                int r = min(r0 + j, NDRAW - 1);
                v[j] = __ldg(&sc[(long)(s_rows[r] + g4)]);
            }
            #pragma unroll
            for (int j = 0; j < 8; j++) {
                float wgt = (r0 + j < NDRAW) ? 1.0f : 0.0f;
                acc.x = fmaf(v[j].x, wgt, acc.x);
                acc.y = fmaf(v[j].y, wgt, acc.y);
                acc.z = fmaf(v[j].z, wgt, acc.z);
                acc.w = fmaf(v[j].w, wgt, acc.w);
            }
        }
    }
    s_acc[w][lane] = acc;
    __syncthreads();

    // ---- phase 2: z = log1p(total), block partial sums (double) ----
    float4 z = make_float4(0.f, 0.f, 0.f, 0.f);
    if (t < 32) {
        float4 tot = make_float4(0.f, 0.f, 0.f, 0.f);
        #pragma unroll
        for (int q = 0; q < NWARP; q++) {
            float4 v = s_acc[q][t];
            tot.x += v.x; tot.y += v.y; tot.z += v.z; tot.w += v.w;
        }
        z.x = log1pf(tot.x); z.y = log1pf(tot.y);
        z.z = log1pf(tot.z); z.w = log1pf(tot.w);
        double ls = 0.0, ls2 = 0.0;
        if (valid) {
            ls  = (double)z.x + (double)z.y + (double)z.z + (double)z.w;
            ls2 = (double)z.x * z.x + (double)z.y * z.y
                + (double)z.z * z.z + (double)z.w * z.w;
        }
        #pragma unroll
        for (int o = 16; o > 0; o >>= 1) {
            ls  += __shfl_down_sync(0xffffffffu, ls, o);
            ls2 += __shfl_down_sync(0xffffffffu, ls2, o);
        }
        if (t == 0) { g_bS[bid] = ls; g_bS2[bid] = ls2; }
    }
    __syncthreads();

    // ---- grid barrier 1: mean / rstd ----
    if (t == 0) {
        __threadfence();
        s_last = (atomicAdd(&g_c1, 1) == GRID_B - 1) ? 1 : 0;
    }
    __syncthreads();
    if (s_last) {
        if (t < 32) {
            double S = 0.0, S2 = 0.0;
            for (int i = t; i < GRID_B; i += 32) {
                S  += ((volatile double*)g_bS)[i];
                S2 += ((volatile double*)g_bS2)[i];
            }
            #pragma unroll
            for (int o = 16; o > 0; o >>= 1) {
                S  += __shfl_down_sync(0xffffffffu, S, o);
                S2 += __shfl_down_sync(0xffffffffu, S2, o);
            }
            if (t == 0) {
                double mean = S / (double)GG;
                double var  = S2 / (double)GG - mean * mean;
                ((volatile float*)g_stats)[0] = (float)mean;
                ((volatile float*)g_stats)[1] = (float)(1.0 / sqrt(var + (double)1e-3f));
                __threadfence();
                atomicExch(&g_flag1, 1);
            }
        }
    } else if (t == 0) {
        while (atomicAdd(&g_flag1, 0) == 0) __nanosleep(40);
    }
    __syncthreads();
    float mean = ((volatile float*)g_stats)[0];
    float rstd = ((volatile float*)g_stats)[1];

    // ---- phase 3: affine + block min/max ----
    float4 zn = make_float4(0.f, 0.f, 0.f, 0.f);
    if (t < 32) {
        float mn = 3.4e38f, mx = -3.4e38f;
        if (valid) {
            float4 gm = __ldg(&gam4[g4]);
            float4 bt = __ldg(&bet4[g4]);
            zn.x = (z.x - mean) * rstd * gm.x + bt.x;
            zn.y = (z.y - mean) * rstd * gm.y + bt.y;
            zn.z = (z.z - mean) * rstd * gm.z + bt.z;
            zn.w = (z.w - mean) * rstd * gm.w + bt.w;
            mn = fminf(fminf(zn.x, zn.y), fminf(zn.z, zn.w));
            mx = fmaxf(fmaxf(zn.x, zn.y), fmaxf(zn.z, zn.w));
        }
        #pragma unroll
        for (int o = 16; o > 0; o >>= 1) {
            mn = fminf(mn, __shfl_down_sync(0xffffffffu, mn, o));
            mx = fmaxf(mx, __shfl_down_sync(0xffffffffu, mx, o));
        }
        if (t == 0) { g_bMin[bid] = mn; g_bMax[bid] = mx; }
    }
    __syncthreads();

    // ---- grid barrier 2: global min / max ----
    if (t == 0) {
        __threadfence();
        s_last = (atomicAdd(&g_c2, 1) == GRID_B - 1) ? 1 : 0;
    }
    __syncthreads();
    if (s_last) {
        if (t < 32) {
            float mn = 3.4e38f, mx = -3.4e38f;
            for (int i = t; i < GRID_B; i += 32) {
                mn = fminf(mn, ((volatile float*)g_bMin)[i]);
                mx = fmaxf(mx, ((volatile float*)g_bMax)[i]);
            }
            #pragma unroll
            for (int o = 16; o > 0; o >>= 1) {
                mn = fminf(mn, __shfl_down_sync(0xffffffffu, mn, o));
                mx = fmaxf(mx, __shfl_down_sync(0xffffffffu, mx, o));
            }
            if (t == 0) {
                ((volatile float*)g_mm)[0] = mn;
                ((volatile float*)g_mm)[1] = mx;
                __threadfence();
                atomicExch(&g_flag2, 1);
            }
        }
    } else if (t == 0) {
        while (atomicAdd(&g_flag2, 0) == 0) __nanosleep(40);
    }
    __syncthreads();

    // ---- phase 4: min-max normalize, write out ----
    if (t < 32 && valid) {
        float lo  = ((volatile float*)g_mm)[0];
        float hi  = ((volatile float*)g_mm)[1];
        float den = hi - lo;
        float4 o;
        if (den == 0.0f) {
            o = make_float4(0.f, 0.f, 0.f, 0.f);
        } else {
            o.x = (zn.x - lo) / den;
            o.y = (zn.y - lo) / den;
            o.z = (zn.z - lo) / den;
            o.w = (zn.w - lo) / den;
        }
        out4[g4] = o;
    }
}

extern "C" void kernel_launch(void* const* d_in, const int* in_sizes, int n_in,
                              void* d_out, int out_size) {
    const float* x   = (const float*)d_in[0];   // (4,64)
    const float* W   = (const float*)d_in[1];   // (64,10)
    const float* b   = (const float*)d_in[2];   // (10,)
    const float* sc  = (const float*)d_in[3];   // (10,1000,18000)
    const float* gam = (const float*)d_in[4];   // (18000,)
    const float* bet = (const float*)d_in[5];   // (18000,)

    k_prep<<<GRID_A, 1024>>>(x, W, b);
    k_fused<<<GRID_B, 512>>>((const float4*)sc, (const float4*)gam,
                             (const float4*)bet, (float4*)d_out);
}